// round 11
// baseline (speedup 1.0000x reference)
#include <cuda_runtime.h>
#include <cuda_bf16.h>

// out[b,o] = sum over UNIQUE keys k=i0*350+i1 in batch row b of W[k,o], + bias[o]
// (reference scatters 1.0 with .set, so duplicate hits count once)
//
// One WARP per batch row: no __syncthreads, no cross-warp smem reduction.
// Each lane handles up to 7 hits; dedup via smem CAS hash (deterministic SET
// of winners); final sum via fixed-pairing shfl_xor butterfly.

#define B      32
#define NHITS  200
#define D1     350
#define OUTN   5
#define HPL    7            // hits per lane: 7*32 = 224 >= 200
#define HSZ    512          // load factor 0.39 (256 blew up: probe clusters)
#define HMASK  (HSZ - 1)
#define EMPTY  (-1)

__global__ __launch_bounds__(32, 1)
void prtnn_kernel(const int* __restrict__ x,
                  const float* __restrict__ W,
                  const float* __restrict__ bias,
                  float* __restrict__ out)
{
    __shared__ int tab[HSZ];

    const int b   = blockIdx.x;
    const int lid = threadIdx.x;

    // ---- Issue all x loads up front (max MLP on the first DRAM/L2 round) ----
    int k[HPL];
    #pragma unroll
    for (int j = 0; j < HPL; ++j) {
        const int idx = j * 32 + lid;
        k[j] = 0;
        if (idx < NHITS) {
            const int* hit = x + (b * NHITS + idx) * 3;
            k[j] = __ldg(hit + 1) * D1 + __ldg(hit + 2);   // 0 .. 2150399
        }
    }

    // Prefetch bias early (lanes 0..4), hidden under the gather rounds.
    float my_bias = 0.f;
    if (lid < OUTN) my_bias = __ldg(bias + lid);

    // Init hash table (16 iters/lane) while x loads are in flight.
    #pragma unroll
    for (int i = lid; i < HSZ; i += 32) tab[i] = EMPTY;
    __syncwarp();

    // ---- Speculative W gathers: two 16B loads per hit, all issued before use.
    // Row [k*5, k*5+5) lies inside the 8-float window at base=(k*5)&~3
    // (16B-aligned; max index 10,751,999 = last element of W, in bounds).
    float a[HPL][8];
    int   r[HPL];
    #pragma unroll
    for (int j = 0; j < HPL; ++j) {
        const int idx = j * 32 + lid;
        r[j] = 0;
        #pragma unroll
        for (int q = 0; q < 8; ++q) a[j][q] = 0.f;
        if (idx < NHITS) {
            const int e    = k[j] * OUTN;       // <= 10,751,995
            const int base = e & ~3;
            r[j] = e & 3;
            const float4 p0 = __ldg((const float4*)(W + base));
            const float4 p1 = __ldg((const float4*)(W + base + 4));
            a[j][0]=p0.x; a[j][1]=p0.y; a[j][2]=p0.z; a[j][3]=p0.w;
            a[j][4]=p1.x; a[j][5]=p1.y; a[j][6]=p1.z; a[j][7]=p1.w;
        }
    }

    // ---- Dedup: CAS insert; winners' identity is schedule-dependent but the
    // SET of unique keys is not. Runs while W loads are in flight.
    float c0=0.f, c1=0.f, c2=0.f, c3=0.f, c4=0.f;
    #pragma unroll
    for (int j = 0; j < HPL; ++j) {
        const int idx = j * 32 + lid;
        bool unique = false;
        if (idx < NHITS) {
            unsigned h = (((unsigned)k[j] * 2654435761u) >> 20) & HMASK;
            while (true) {
                int old = atomicCAS(&tab[h], EMPTY, k[j]);
                if (old == EMPTY) { unique = true; break; }
                if (old == k[j])  { break; }
                h = (h + 1) & HMASK;
            }
        }
        if (unique) {
            const int rr = r[j];
            // Predicated selects (no register-indexed arrays -> no spills).
            const float w0 = (rr==0)?a[j][0]:(rr==1)?a[j][1]:(rr==2)?a[j][2]:a[j][3];
            const float w1 = (rr==0)?a[j][1]:(rr==1)?a[j][2]:(rr==2)?a[j][3]:a[j][4];
            const float w2 = (rr==0)?a[j][2]:(rr==1)?a[j][3]:(rr==2)?a[j][4]:a[j][5];
            const float w3 = (rr==0)?a[j][3]:(rr==1)?a[j][4]:(rr==2)?a[j][5]:a[j][6];
            const float w4 = (rr==0)?a[j][4]:(rr==1)?a[j][5]:(rr==2)?a[j][6]:a[j][7];
            c0 += w0; c1 += w1; c2 += w2; c3 += w3; c4 += w4;
        }
    }

    // ---- Deterministic butterfly reduction: all lanes end with the total.
    #pragma unroll
    for (int s = 16; s > 0; s >>= 1) {
        c0 += __shfl_xor_sync(0xFFFFFFFFu, c0, s);
        c1 += __shfl_xor_sync(0xFFFFFFFFu, c1, s);
        c2 += __shfl_xor_sync(0xFFFFFFFFu, c2, s);
        c3 += __shfl_xor_sync(0xFFFFFFFFu, c3, s);
        c4 += __shfl_xor_sync(0xFFFFFFFFu, c4, s);
    }

    if (lid < OUTN) {
        const float v = (lid==0)?c0:(lid==1)?c1:(lid==2)?c2:(lid==3)?c3:c4;
        out[b * OUTN + lid] = v + my_bias;
    }
}

extern "C" void kernel_launch(void* const* d_in, const int* in_sizes, int n_in,
                              void* d_out, int out_size)
{
    const int*   x    = (const int*)d_in[0];    // [32, 200, 3] int32
    const float* W    = (const float*)d_in[1];  // [2150400, 5] f32
    const float* bias = (const float*)d_in[2];  // [5] f32
    float*       out  = (float*)d_out;          // [32, 5] f32

    prtnn_kernel<<<B, 32>>>(x, W, bias, out);
}